// round 1
// baseline (speedup 1.0000x reference)
#include <cuda_runtime.h>
#include <math.h>

#define B_ 16
#define C_ 64          // Cin = Cout
#define HW_ 64
#define E_ 16
#define KTOP_ 4
#define WPE_ (64*64*9) // weights per expert = 36864

// ---------------- scratch (device globals; no allocations allowed) ----------
__device__ float g_gate_x[B_ * C_];          // (b, ci) means
__device__ float g_gates[B_ * E_];           // dense gates
__device__ float g_beff[B_ * C_];            // effective bias per (b, co)
__device__ float g_Weff[B_ * WPE_];          // effective weights per batch (9.4 MB)

// ---------------- kernel 1: gate_x = mean over HxW -------------------------
__global__ __launch_bounds__(256) void mean_kernel(const float* __restrict__ x) {
    const int bc = blockIdx.x;                 // b*64 + ci  (1024 blocks)
    const float* p = x + (size_t)bc * (HW_ * HW_);
    float s = 0.f;
    for (int i = threadIdx.x; i < HW_ * HW_; i += 256) s += p[i];
    // warp reduce
    for (int o = 16; o > 0; o >>= 1) s += __shfl_xor_sync(0xffffffffu, s, o);
    __shared__ float red[8];
    if ((threadIdx.x & 31) == 0) red[threadIdx.x >> 5] = s;
    __syncthreads();
    if (threadIdx.x == 0) {
        float t = 0.f;
        #pragma unroll
        for (int w = 0; w < 8; w++) t += red[w];
        g_gate_x[bc] = t * (1.0f / (HW_ * HW_));
    }
}

// ---------------- kernel 2: gating + top-k + loss + beff --------------------
__global__ __launch_bounds__(256) void gate_kernel(const float* __restrict__ w_gate,
                                                   const float* __restrict__ bias,
                                                   float* __restrict__ loss_out) {
    __shared__ float logit[B_][E_];
    __shared__ float sg[B_][E_];
    const int tid = threadIdx.x;            // 256 = 16*16
    const int b = tid >> 4, e = tid & 15;

    // logits = gate_x @ w_gate   (w_gate is (Cin, E) row-major)
    float s = 0.f;
    #pragma unroll 8
    for (int ci = 0; ci < C_; ci++) s += g_gate_x[b * C_ + ci] * w_gate[ci * E_ + e];
    logit[b][e] = s;
    sg[b][e] = 0.f;
    __syncthreads();

    if (tid < B_) {
        const int bb = tid;
        float mx = -1e30f;
        #pragma unroll
        for (int j = 0; j < E_; j++) mx = fmaxf(mx, logit[bb][j]);
        float p[E_]; float sum = 0.f;
        #pragma unroll
        for (int j = 0; j < E_; j++) { p[j] = __expf(logit[bb][j] - mx); sum += p[j]; }
        const float inv = 1.0f / sum;
        #pragma unroll
        for (int j = 0; j < E_; j++) p[j] *= inv;
        // top-4 by value (first-index tiebreak matches lax.top_k)
        bool used[E_] = {false};
        float tv[KTOP_]; int ti[KTOP_]; float tsum = 0.f;
        #pragma unroll
        for (int k = 0; k < KTOP_; k++) {
            float best = -1.f; int bi = 0;
            #pragma unroll
            for (int j = 0; j < E_; j++)
                if (!used[j] && p[j] > best) { best = p[j]; bi = j; }
            used[bi] = true; tv[k] = best; ti[k] = bi; tsum += best;
        }
        const float denom = 1.0f / (tsum + 1e-6f);
        #pragma unroll
        for (int k = 0; k < KTOP_; k++) sg[bb][ti[k]] = tv[k] * denom;
    }
    __syncthreads();

    g_gates[tid] = sg[b][e];

    if (tid == 0) {
        float mi = 0.f, ml = 0.f;
        float imp[E_], ld[E_];
        for (int j = 0; j < E_; j++) {
            float si = 0.f, sl = 0.f;
            for (int bb = 0; bb < B_; bb++) {
                float g = sg[bb][j];
                si += g;
                sl += (g > 0.f) ? 1.f : 0.f;
            }
            imp[j] = si; ld[j] = sl; mi += si; ml += sl;
        }
        mi *= (1.0f / E_); ml *= (1.0f / E_);
        float vi = 0.f, vl = 0.f;
        for (int j = 0; j < E_; j++) {
            float di = imp[j] - mi, dl = ld[j] - ml;
            vi += di * di; vl += dl * dl;
        }
        vi *= (1.0f / (E_ - 1)); vl *= (1.0f / (E_ - 1));
        float cvi = vi / (mi * mi + 1e-10f);
        float cvl = vl / (ml * ml + 1e-10f);
        loss_out[0] = (cvi + cvl) * 0.01f;
    }
    __syncthreads();

    // effective bias: beff[b][co] = sum_e g[b][e] * bias[e][co]
    for (int idx = tid; idx < B_ * C_; idx += 256) {
        const int bb = idx >> 6, co = idx & 63;
        float s2 = 0.f;
        #pragma unroll
        for (int ee = 0; ee < E_; ee++) s2 += sg[bb][ee] * bias[ee * C_ + co];
        g_beff[idx] = s2;
    }
}

// ---------------- kernel 3: Weff[b] = sum_e g[b,e] * W[e] -------------------
__global__ __launch_bounds__(256) void weff_kernel(const float* __restrict__ W) {
    const int b = blockIdx.y;
    const int i = blockIdx.x * 256 + threadIdx.x;    // < 36864
    if (i >= WPE_) return;
    float s = 0.f;
    #pragma unroll
    for (int e = 0; e < E_; e++) s += g_gates[b * E_ + e] * W[(size_t)e * WPE_ + i];
    g_Weff[(size_t)b * WPE_ + i] = s;
}

// ---------------- kernel 4: per-batch conv with blended weights -------------
// grid: (8 row-tiles, 4 co-tiles, 16 batches); block 256 threads
// thread -> (co_l = tid>>4 in [0,16), cq = tid&15 -> output cols cq*4..cq*4+3)
// output tile per block: 16 co x 8 rows x 64 cols
__global__ __launch_bounds__(256) void conv_kernel(const float* __restrict__ x,
                                                   float* __restrict__ out) {
    const int b = blockIdx.z;
    const int co_base = blockIdx.y * 16;
    const int row_base = blockIdx.x * 8;
    const int tid = threadIdx.x;
    const int co_l = tid >> 4;
    const int cq = tid & 15;
    const int c0 = cq * 4;

    __shared__ float xs[16][10][66];   // ci-chunk x (8 rows + halo) x (64 cols + halo)
    __shared__ float ws[16][16][9];    // [co_l][ci_l][tap]

    float acc[8][4];
    #pragma unroll
    for (int r = 0; r < 8; r++)
        #pragma unroll
        for (int j = 0; j < 4; j++) acc[r][j] = 0.f;

    const float* xb = x + (size_t)b * C_ * HW_ * HW_;
    const float* wb = g_Weff + (size_t)b * WPE_;

    for (int cc = 0; cc < C_; cc += 16) {
        // ---- stage x chunk with zero-padded halo ----
        for (int idx = tid; idx < 16 * 10 * 66; idx += 256) {
            const int ci = idx / 660;
            const int rem = idx - ci * 660;
            const int r = rem / 66;
            const int c = rem - r * 66;
            const int gr = row_base - 1 + r;
            const int gc = c - 1;
            float v = 0.f;
            if (gr >= 0 && gr < HW_ && gc >= 0 && gc < HW_)
                v = xb[((cc + ci) * HW_ + gr) * HW_ + gc];
            xs[ci][r][c] = v;
        }
        // ---- stage weights ----
        for (int idx = tid; idx < 16 * 16 * 9; idx += 256) {
            const int col = idx / 144;
            const int rem = idx - col * 144;
            const int ci = rem / 9;
            const int k = rem - ci * 9;
            ws[col][ci][k] = wb[((co_base + col) * C_ + cc + ci) * 9 + k];
        }
        __syncthreads();

        #pragma unroll 1
        for (int ci = 0; ci < 16; ci++) {
            float w[9];
            #pragma unroll
            for (int k = 0; k < 9; k++) w[k] = ws[co_l][ci][k];
            #pragma unroll
            for (int lr = 0; lr < 10; lr++) {
                float xw[6];
                #pragma unroll
                for (int j = 0; j < 6; j++) xw[j] = xs[ci][lr][c0 + j];
                // input row lr feeds output rows lr-2..lr (dy = lr - ro)
                #pragma unroll
                for (int dy = 0; dy < 3; dy++) {
                    const int ro = lr - dy;
                    if (ro >= 0 && ro < 8) {
                        #pragma unroll
                        for (int j = 0; j < 4; j++) {
                            acc[ro][j] = fmaf(w[dy * 3 + 0], xw[j + 0], acc[ro][j]);
                            acc[ro][j] = fmaf(w[dy * 3 + 1], xw[j + 1], acc[ro][j]);
                            acc[ro][j] = fmaf(w[dy * 3 + 2], xw[j + 2], acc[ro][j]);
                        }
                    }
                }
            }
        }
        __syncthreads();
    }

    const int co = co_base + co_l;
    const float bias = g_beff[b * C_ + co];
    #pragma unroll
    for (int ro = 0; ro < 8; ro++) {
        float4 v;
        v.x = acc[ro][0] + bias;
        v.y = acc[ro][1] + bias;
        v.z = acc[ro][2] + bias;
        v.w = acc[ro][3] + bias;
        *(float4*)&out[(((size_t)b * C_ + co) * HW_ + row_base + ro) * HW_ + c0] = v;
    }
}

// ---------------- launch --------------------------------------------------
extern "C" void kernel_launch(void* const* d_in, const int* in_sizes, int n_in,
                              void* d_out, int out_size) {
    const float* x      = (const float*)d_in[0];   // (16,64,64,64)
    const float* w_gate = (const float*)d_in[1];   // (64,16)
    // d_in[2] = w_noise  (unused: train==0 path never uses it)
    const float* W      = (const float*)d_in[3];   // (16,64,64,3,3)
    const float* bias   = (const float*)d_in[4];   // (16,64)
    float* out = (float*)d_out;                    // y flat (4194304) then loss

    mean_kernel<<<B_ * C_, 256>>>(x);
    gate_kernel<<<1, 256>>>(w_gate, bias, out + (out_size - 1));
    {
        dim3 g((WPE_ + 255) / 256, B_);
        weff_kernel<<<g, 256>>>(W);
    }
    {
        dim3 g(8, 4, B_);
        conv_kernel<<<g, 256>>>(x, out);
    }
}